// round 13
// baseline (speedup 1.0000x reference)
#include <cuda_runtime.h>
#include <cuda_bf16.h>

// Problem constants (reference: NUM_CLASSES=5532, F=256, Q=2*NUM_CLASSES, N=131072)
#define NC    5532
#define FEAT  256
#define NV4   (FEAT / 4)     // 64 float4 per row
#define RCAP  32             // per-replica bucket capacity (Poisson(~6)/replica)
#define CAP   (4 * RCAP)     // 128 rows per class
#define BKT_BLOCKS  128      // int4 bucket blocks (128*256*4 = 131072 labels)
#define COPY_BLOCKS 1024     // copy blocks in the same prep launch

// Scratch (device globals; zero-initialized at load, self-resetting per call)
__device__ int4 g_cnt4[NC];          // striped per-class counts (4 replicas)
__device__ int  g_pos[NC];           // final queue row for present classes
__device__ int  g_bucket[NC * CAP];  // row indices: [class][replica][slot]
__device__ int  g_flag;              // scan-done release flag

// ---------------------------------------------------------------------------
// 1) PREP (measured ~9.1us): blocks [0,128) ticket labels with 4 independent
//    atomic chains per thread (int4 load; replica = position-in-int4).
//    Blocks [128,1152) copy the FULL output (queue + labels) — 23MB of
//    bandwidth work hiding inside the bucket phase's latency (DRAM was 0.9%
//    for the bucket alone). One copy block also resets the scan flag.
// ---------------------------------------------------------------------------
__global__ void prep_kernel(const int4* __restrict__ labels4, int N4,
                            const float4* __restrict__ queue_in,
                            const float4* __restrict__ label_in,
                            float4* __restrict__ out4,
                            int nq4, int nl4) {
    if (blockIdx.x < BKT_BLOCKS) {
        int i = blockIdx.x * blockDim.x + threadIdx.x;
        if (i < N4) {
            int4 L = labels4[i];
            int base = i * 4;
            int* cnt = (int*)g_cnt4;
            int cs[4] = {L.x, L.y, L.z, L.w};
#pragma unroll
            for (int k = 0; k < 4; k++) {
                int c = cs[k];
                if (c >= 0 && c < NC) {
                    int s = atomicAdd(&cnt[c * 4 + k], 1);
                    if (s < RCAP) g_bucket[c * CAP + k * RCAP + s] = base + k;
                }
            }
        }
    } else {
        if (blockIdx.x == BKT_BLOCKS && threadIdx.x == 0) g_flag = 0;
        int total = nq4 + nl4;
        int stride = COPY_BLOCKS * blockDim.x;
        for (int i = (blockIdx.x - BKT_BLOCKS) * blockDim.x + threadIdx.x;
             i < total; i += stride) {
            float4 v = __ldcs((i < nq4) ? (queue_in + i)
                                        : (label_in + (i - nq4)));
            __stcs(out4 + i, v);
        }
    }
}

// ---------------------------------------------------------------------------
// 2) SCAN + MEAN in one kernel.
//    Block 0: presence scan (64 threads, ~87 classes each) -> g_pos, then
//    __threadfence + flag=1 (release). Runs concurrently with the gathers.
//    Blocks 1..NC: class c = bid-1. Gather rows (default-cached loads —
//    features stay L2-resident across graph replays, measured 5.1 TB/s),
//    then WAIT on the flag (poll+nanosleep; block 0 is in wave 1 so this
//    cannot deadlock), read g_pos, write the mean + label, and only then
//    reset the class counter (so the scan's count reads can't race it).
// ---------------------------------------------------------------------------
__global__ void __launch_bounds__(64) mean_scan_kernel(
        const float4* __restrict__ feat,
        const int* __restrict__ labels, int N,
        const int* __restrict__ tail_p,
        float* __restrict__ out, int Q) {
    int t = threadIdx.x;

    if (blockIdx.x == 0) {
        // ---- scan role ----
        const int CHUNK = (NC + 63) / 64;    // 87
        int lane = t & 31;
        int w    = t >> 5;
        int base = t * CHUNK;

        int lp = 0;
        for (int k = 0; k < CHUNK; k++) {
            int c = base + k;
            if (c < NC) {
                int4 cv = g_cnt4[c];
                if ((cv.x | cv.y | cv.z | cv.w) != 0) lp++;
            }
        }
        int ip = lp;
#pragma unroll
        for (int off = 1; off < 32; off <<= 1) {
            int v = __shfl_up_sync(0xffffffffu, ip, off);
            if (lane >= off) ip += v;
        }
        __shared__ int wsum;
        if (w == 0 && lane == 31) wsum = ip;
        __syncthreads();
        int offp = ip - lp + (w ? wsum : 0);

        int tail = *tail_p;
        int ws = tail % Q; if (ws < 0) ws += Q;

        for (int k = 0; k < CHUNK; k++) {
            int c = base + k;
            if (c < NC) {
                int4 cv = g_cnt4[c];
                if ((cv.x | cv.y | cv.z | cv.w) != 0) {
                    int pos = ws + offp;
                    if (pos >= Q) pos -= Q;
                    g_pos[c] = pos;
                    offp++;
                }
            }
        }
        __threadfence();                 // release g_pos
        __syncthreads();
        if (t == 0) g_flag = 1;
        return;
    }

    // ---- mean role ----
    __shared__ int sidx[CAP];
    int c = blockIdx.x - 1;

    int4 cv = g_cnt4[c];                 // final (written by prior kernel)
    int cnt = cv.x + cv.y + cv.z + cv.w;
    if (cnt == 0) return;                // uniform

    float4 acc = make_float4(0.f, 0.f, 0.f, 0.f);
    bool ovf = (cv.x > RCAP) | (cv.y > RCAP) | (cv.z > RCAP) | (cv.w > RCAP);

    if (!ovf) {
        int cr[4] = {cv.x, cv.y, cv.z, cv.w};
        int off = 0;
#pragma unroll
        for (int r = 0; r < 4; r++) {
            if (t < cr[r]) sidx[off + t] = g_bucket[c * CAP + r * RCAP + t];
            off += cr[r];
        }
        __syncthreads();

        int r = 0;
        for (; r + 8 <= cnt; r += 8) {
            float4 v0 = feat[(size_t)sidx[r + 0] * NV4 + t];
            float4 v1 = feat[(size_t)sidx[r + 1] * NV4 + t];
            float4 v2 = feat[(size_t)sidx[r + 2] * NV4 + t];
            float4 v3 = feat[(size_t)sidx[r + 3] * NV4 + t];
            float4 v4 = feat[(size_t)sidx[r + 4] * NV4 + t];
            float4 v5 = feat[(size_t)sidx[r + 5] * NV4 + t];
            float4 v6 = feat[(size_t)sidx[r + 6] * NV4 + t];
            float4 v7 = feat[(size_t)sidx[r + 7] * NV4 + t];
            acc.x += (v0.x + v1.x) + (v2.x + v3.x) + (v4.x + v5.x) + (v6.x + v7.x);
            acc.y += (v0.y + v1.y) + (v2.y + v3.y) + (v4.y + v5.y) + (v6.y + v7.y);
            acc.z += (v0.z + v1.z) + (v2.z + v3.z) + (v4.z + v5.z) + (v6.z + v7.z);
            acc.w += (v0.w + v1.w) + (v2.w + v3.w) + (v4.w + v5.w) + (v6.w + v7.w);
        }
        for (; r < cnt; r++) {
            float4 v = feat[(size_t)sidx[r] * NV4 + t];
            acc.x += v.x; acc.y += v.y; acc.z += v.z; acc.w += v.w;
        }
    } else {
        // Generic fallback: rescan all labels (correct for any input).
        for (int i = 0; i < N; i++) {
            if (__ldg(&labels[i]) == c) {
                float4 v = feat[(size_t)i * NV4 + t];
                acc.x += v.x; acc.y += v.y; acc.z += v.z; acc.w += v.w;
            }
        }
    }

    // ---- wait for the scan's release flag (usually already set) ----
    if (t == 0) {
        while (((volatile int*)&g_flag)[0] == 0) __nanosleep(64);
    }
    __syncthreads();
    __threadfence();                     // acquire: order g_pos read after flag

    int pos = g_pos[c];
    float inv = 1.0f / (float)cnt;
    float4 o = make_float4(acc.x * inv, acc.y * inv, acc.z * inv, acc.w * inv);
    __stcs((float4*)out + (size_t)pos * NV4 + t, o);
    if (t == 0) {
        out[(size_t)Q * FEAT + pos] = (float)c;
        g_cnt4[c] = make_int4(0, 0, 0, 0);   // reset AFTER scan is done
    }
}

// ---------------------------------------------------------------------------
// Launch.  Inputs: features f32[N,256], pid_labels i32[N],
//   large_batch_queue f32[Q,256], queue_label f32[Q], tail i32[1]
// Output: [new_queue f32[Q,256] | new_label f32[Q]]
// ---------------------------------------------------------------------------
extern "C" void kernel_launch(void* const* d_in, const int* in_sizes, int n_in,
                              void* d_out, int out_size) {
    const float4* feat    = (const float4*)d_in[0];
    const int*    labels  = (const int*)d_in[1];
    const float4* queue0  = (const float4*)d_in[2];
    const float4* qlabel0 = (const float4*)d_in[3];
    const int*    tail_p  = (const int*)d_in[4];

    int N = in_sizes[1];              // 131072 (divisible by 4)
    int Q = in_sizes[3];              // 11064 (divisible by 4)
    float* out = (float*)d_out;

    // 1) fused bucket (int4 tickets) + full output copy + flag reset
    {
        int nq4 = Q * NV4;
        int nl4 = Q / 4;
        prep_kernel<<<BKT_BLOCKS + COPY_BLOCKS, 256>>>(
            (const int4*)labels, N / 4, queue0, qlabel0, (float4*)out,
            nq4, nl4);
    }
    // 2) scan (block 0, hidden) + per-class gather/mean/scatter
    mean_scan_kernel<<<1 + NC, 64>>>(feat, labels, N, tail_p, out, Q);
}